// round 4
// baseline (speedup 1.0000x reference)
#include <cuda_runtime.h>

#define M_TOK 4096
#define DM    64
#define NH    8
#define HD    8
#define DFF   256
#define NLAYER 4
#define KSPLIT 2

// ---------------- scratch (device globals; no allocation allowed) ----------------
__device__ __align__(16) float g_X   [M_TOK*DM];
__device__ __align__(16) float g_QKV [3*NH*M_TOK*HD];
__device__ __align__(16) float g_ATT [M_TOK*DM];
__device__ __align__(16) float g_F1  [M_TOK*DFF];
__device__ __align__(16) float g_PACC[KSPLIT*M_TOK*DM];
__device__ __align__(16) float g_PSUM[KSPLIT*NH*M_TOK];
__device__ __align__(16) float g_XP  [M_TOK*DM];
__device__ float g_NX[M_TOK];
__device__ float g_NY[M_TOK];
__device__ float g_PART[3*128];
__device__ int   g_kd;

// Fast exp on the FMA pipe (avoids MUFU throughput wall). ~2e-6 rel err.
__device__ __forceinline__ float fexp(float x){
    x = fmaxf(x, -80.f);
    float t  = fmaf(x, 1.4426950408889634f, 12582912.f); // round(x*log2e) in mantissa
    float fn = t - 12582912.f;
    float f  = fmaf(x, 1.4426950408889634f, -fn);        // frac in [-0.5,0.5]
    float p  = 1.3333558146e-3f;
    p = fmaf(p, f, 9.618129107e-3f);
    p = fmaf(p, f, 5.550410866e-2f);
    p = fmaf(p, f, 2.402264923e-1f);
    p = fmaf(p, f, 6.9314718056e-1f);
    p = fmaf(p, f, 1.0f);
    int i = __float_as_int(t) - 0x4B400000;              // integer exponent n
    return __int_as_float(__float_as_int(p) + (i << 23));
}

__device__ __forceinline__ float dot4(float4 a, float4 b, float acc){
    acc = fmaf(a.x, b.x, acc); acc = fmaf(a.y, b.y, acc);
    acc = fmaf(a.z, b.z, acc); acc = fmaf(a.w, b.w, acc);
    return acc;
}

// ---------------- generic skinny GEMM: C = A[4096,K] @ W[ncols,K]^T + b ----------
// EPI 0: scatter to Q/K/V head layout (q scaled by 1/sqrt(hd))
// EPI 1: ReLU, store to OUT[m*ldo + col]
// EPI 2: + residual, LayerNorm -> OUT[m*64 + col]   (grid.y must be 1)
template<int KDIM, int EPI>
__global__ __launch_bounds__(256) void k_gemm(
    const float* __restrict__ A, int lda,
    const float* __restrict__ W,
    const float* __restrict__ bias,
    const float* __restrict__ RES,
    const float* __restrict__ lnw, const float* __restrict__ lnb,
    float* __restrict__ OUT, int ldo)
{
    __shared__ __align__(16) float Asm[32][68];
    __shared__ float WsmT[64][66];
    const int tid = threadIdx.x;
    const int rb  = blockIdx.x * 32;
    const int cb  = blockIdx.y * 64;
    const int c0  = tid & 31;
    const int rbase = (tid >> 5) * 4;
    float acc[4][2] = {};
    const int ldq = lda >> 2;

    #pragma unroll
    for (int ch = 0; ch < KDIM/64; ch++){
        const float4* A4 = (const float4*)(A + (size_t)rb*lda + ch*64);
        for (int idx = tid; idx < 512; idx += 256){
            int r = idx >> 4, kq = idx & 15;
            *(float4*)&Asm[r][kq*4] = A4[(size_t)r*ldq + kq];
        }
        for (int idx = tid; idx < 4096; idx += 256){
            int c = idx >> 6, k = idx & 63;
            WsmT[k][c] = W[(size_t)(cb + c)*KDIM + ch*64 + k];
        }
        __syncthreads();
        #pragma unroll 4
        for (int k = 0; k < 64; k += 4){
            float4 a0 = *(const float4*)&Asm[rbase+0][k];
            float4 a1 = *(const float4*)&Asm[rbase+1][k];
            float4 a2 = *(const float4*)&Asm[rbase+2][k];
            float4 a3 = *(const float4*)&Asm[rbase+3][k];
            #pragma unroll
            for (int kk = 0; kk < 4; kk++){
                float w0 = WsmT[k+kk][c0];
                float w1 = WsmT[k+kk][c0+32];
                float av0 = (&a0.x)[kk], av1 = (&a1.x)[kk], av2 = (&a2.x)[kk], av3 = (&a3.x)[kk];
                acc[0][0]=fmaf(av0,w0,acc[0][0]); acc[0][1]=fmaf(av0,w1,acc[0][1]);
                acc[1][0]=fmaf(av1,w0,acc[1][0]); acc[1][1]=fmaf(av1,w1,acc[1][1]);
                acc[2][0]=fmaf(av2,w0,acc[2][0]); acc[2][1]=fmaf(av2,w1,acc[2][1]);
                acc[3][0]=fmaf(av3,w0,acc[3][0]); acc[3][1]=fmaf(av3,w1,acc[3][1]);
            }
        }
        __syncthreads();
    }

    const float qs = (EPI == 0 && blockIdx.y == 0) ? 0.35355339059327373f : 1.0f;
    #pragma unroll
    for (int i = 0; i < 4; i++){
        int m = rb + rbase + i;
        #pragma unroll
        for (int u = 0; u < 2; u++){
            int c = c0 + 32*u;
            float v = acc[i][u] + bias[cb + c];
            if (EPI == 0){
                v *= qs;
                int head = c >> 3, jj = c & 7;
                OUT[(((int)blockIdx.y*NH + head)*M_TOK + m)*HD + jj] = v;
            } else if (EPI == 1){
                OUT[(size_t)m*ldo + cb + c] = fmaxf(v, 0.f);
            } else {
                Asm[rbase+i][c] = v + RES[m*DM + c];
            }
        }
    }
    if (EPI == 2){
        __syncthreads();
        int row = tid >> 3, seg = tid & 7;
        float s = 0.f, s2 = 0.f;
        #pragma unroll
        for (int t = 0; t < 8; t++){
            float x = Asm[row][seg*8 + t];
            s += x; s2 = fmaf(x, x, s2);
        }
        #pragma unroll
        for (int off = 4; off > 0; off >>= 1){
            s  += __shfl_xor_sync(0xffffffffu, s,  off);
            s2 += __shfl_xor_sync(0xffffffffu, s2, off);
        }
        float mean = s * (1.f/64.f);
        float var  = fmaf(-mean, mean, s2 * (1.f/64.f));
        float rstd = rsqrtf(var + 1e-5f);
        int m = rb + row;
        #pragma unroll
        for (int t = 0; t < 8; t++){
            int c = seg*8 + t;
            OUT[m*DM + c] = (Asm[row][c] - mean) * rstd * lnw[c] + lnb[c];
        }
    }
}

// ---------------- attention: no-max softmax (logits tiny), additive split-K -----
__global__ __launch_bounds__(128) void k_attn(const float* __restrict__ QKV)
{
    __shared__ float4 Ks[512*2];
    __shared__ float4 Vs[512*2];
    const int tid = threadIdx.x;
    const int h   = blockIdx.y;
    const int m   = blockIdx.x*128 + tid;
    const int ks  = blockIdx.z;
    const float4* Q4 = (const float4*)QKV + (size_t)(h*M_TOK + m)*2;
    const float4* K4 = (const float4*)QKV + (size_t)(NH*M_TOK + h*M_TOK)*2;
    const float4* V4 = (const float4*)QKV + (size_t)(2*NH*M_TOK + h*M_TOK)*2;
    float4 q0 = Q4[0], q1 = Q4[1];
    float4 a0 = {0,0,0,0}, a1 = {0,0,0,0};
    float ssum = 0.f;

    for (int kt = 0; kt < 4; kt++){
        int key0 = ks*2048 + kt*512;
        for (int idx = tid; idx < 1024; idx += 128){
            Ks[idx] = K4[key0*2 + idx];
            Vs[idx] = V4[key0*2 + idx];
        }
        __syncthreads();
        #pragma unroll 4
        for (int j = 0; j < 512; j++){
            float4 k0 = Ks[2*j], k1 = Ks[2*j+1];
            float s = q0.x*k0.x;
            s = fmaf(q0.y,k0.y,s); s = fmaf(q0.z,k0.z,s); s = fmaf(q0.w,k0.w,s);
            s = fmaf(q1.x,k1.x,s); s = fmaf(q1.y,k1.y,s);
            s = fmaf(q1.z,k1.z,s); s = fmaf(q1.w,k1.w,s);
            float p = fexp(s);
            ssum += p;
            float4 v0 = Vs[2*j], v1 = Vs[2*j+1];
            a0.x = fmaf(p,v0.x,a0.x); a0.y = fmaf(p,v0.y,a0.y);
            a0.z = fmaf(p,v0.z,a0.z); a0.w = fmaf(p,v0.w,a0.w);
            a1.x = fmaf(p,v1.x,a1.x); a1.y = fmaf(p,v1.y,a1.y);
            a1.z = fmaf(p,v1.z,a1.z); a1.w = fmaf(p,v1.w,a1.w);
        }
        __syncthreads();
    }
    float* PA = g_PACC + (size_t)ks*M_TOK*DM + (size_t)m*DM + h*HD;
    ((float4*)PA)[0] = a0; ((float4*)PA)[1] = a1;
    g_PSUM[ks*NH*M_TOK + h*M_TOK + m] = ssum;
}

__global__ __launch_bounds__(256) void k_comb(float* __restrict__ ATT)
{
    int idx = blockIdx.x*256 + threadIdx.x;
    int m = idx >> 6, c = idx & 63, h = c >> 3;
    float s = g_PSUM[h*M_TOK + m] + g_PSUM[NH*M_TOK + h*M_TOK + m];
    ATT[idx] = (g_PACC[idx] + g_PACC[M_TOK*DM + idx]) / s;
}

// ---------------- prune + row norms (+ detect mask support, for dot shortcut) ---
__global__ __launch_bounds__(64) void k_pn(const float* __restrict__ X,
                                           const float* __restrict__ RGB,
                                           const float* __restrict__ mask,
                                           float* __restrict__ dout)
{
    __shared__ float w0x, w0y;
    __shared__ int anyhi;
    int r = blockIdx.x, d = threadIdx.x;
    float xv = X[r*DM + d] * mask[d];
    g_XP[r*DM + d] = xv;
    dout[r*DM + d] = xv;
    float yv = RGB[r*DM + d];
    float sx = xv*xv, sy = yv*yv;
    #pragma unroll
    for (int off = 16; off > 0; off >>= 1){
        sx += __shfl_xor_sync(0xffffffffu, sx, off);
        sy += __shfl_xor_sync(0xffffffffu, sy, off);
    }
    if (d == 0){ w0x = sx; w0y = sy; }
    if (r == 0 && d == 0) anyhi = 0;
    __syncthreads();
    if (d == 32){ g_NX[r] = w0x + sx; g_NY[r] = w0y + sy; }
    if (r == 0){
        if (d >= 32 && mask[d] != 0.f) anyhi = 1;
        __syncthreads();
        if (d == 0) g_kd = anyhi ? 64 : 32;
    }
}

// ---------------- Gaussian-kernel gram sums --------------------------------------
template<int KD>
__device__ __forceinline__ float mmd_tile(const float Asm[32][68], const float Bsm[128][68],
                                          const float* na, const float* nb,
                                          int rbase, int ja)
{
    float acc[4][4] = {};
    #pragma unroll 4
    for (int k = 0; k < KD; k += 4){
        float4 a0 = *(const float4*)&Asm[rbase+0][k];
        float4 a1 = *(const float4*)&Asm[rbase+1][k];
        float4 a2 = *(const float4*)&Asm[rbase+2][k];
        float4 a3 = *(const float4*)&Asm[rbase+3][k];
        float4 b0 = *(const float4*)&Bsm[ja     ][k];
        float4 b1 = *(const float4*)&Bsm[ja+ 32 ][k];
        float4 b2 = *(const float4*)&Bsm[ja+ 64 ][k];
        float4 b3 = *(const float4*)&Bsm[ja+ 96 ][k];
        acc[0][0]=dot4(a0,b0,acc[0][0]); acc[0][1]=dot4(a0,b1,acc[0][1]);
        acc[0][2]=dot4(a0,b2,acc[0][2]); acc[0][3]=dot4(a0,b3,acc[0][3]);
        acc[1][0]=dot4(a1,b0,acc[1][0]); acc[1][1]=dot4(a1,b1,acc[1][1]);
        acc[1][2]=dot4(a1,b2,acc[1][2]); acc[1][3]=dot4(a1,b3,acc[1][3]);
        acc[2][0]=dot4(a2,b0,acc[2][0]); acc[2][1]=dot4(a2,b1,acc[2][1]);
        acc[2][2]=dot4(a2,b2,acc[2][2]); acc[2][3]=dot4(a2,b3,acc[2][3]);
        acc[3][0]=dot4(a3,b0,acc[3][0]); acc[3][1]=dot4(a3,b1,acc[3][1]);
        acc[3][2]=dot4(a3,b2,acc[3][2]); acc[3][3]=dot4(a3,b3,acc[3][3]);
    }
    float psum = 0.f;
    #pragma unroll
    for (int i = 0; i < 4; i++){
        float nai = na[rbase+i];
        #pragma unroll
        for (int u = 0; u < 4; u++){
            float d = nai + nb[ja + 32*u] - 2.f*acc[i][u];
            psum += fexp(-0.5f*d);
        }
    }
    return psum;
}

__global__ __launch_bounds__(256) void k_mmd(const float* __restrict__ RGB)
{
    __shared__ __align__(16) float Asm[32][68];
    __shared__ __align__(16) float Bsm[128][68];
    __shared__ float na[32], nb[128], red[256];
    const int type = blockIdx.y;
    const float *A, *B, *NA, *NB;
    if (type == 0){ A = g_XP; B = g_XP; NA = g_NX; NB = g_NX; }
    else if (type == 1){ A = RGB; B = RGB; NA = g_NY; NB = g_NY; }
    else { A = g_XP; B = RGB; NA = g_NX; NB = g_NY; }
    const int kd = (type == 1) ? 64 : g_kd;

    const int tid = threadIdx.x;
    const int ib  = blockIdx.x * 32;
    for (int idx = tid; idx < 512; idx += 256){
        int r = idx >> 4, kq = idx & 15;
        *(float4*)&Asm[r][kq*4] = ((const float4*)A)[(ib + r)*16 + kq];
    }
    if (tid < 32) na[tid] = NA[ib + tid];

    const int ja = tid & 31, rbase = (tid >> 5) * 4;
    float psum = 0.f;
    for (int jt = 0; jt < 32; jt++){
        __syncthreads();
        for (int idx = tid; idx < 2048; idx += 256){
            int r = idx >> 4, kq = idx & 15;
            *(float4*)&Bsm[r][kq*4] = ((const float4*)B)[(jt*128 + r)*16 + kq];
        }
        if (tid < 128) nb[tid] = NB[jt*128 + tid];
        __syncthreads();
        if (kd == 32) psum += mmd_tile<32>(Asm, Bsm, na, nb, rbase, ja);
        else          psum += mmd_tile<64>(Asm, Bsm, na, nb, rbase, ja);
    }
    red[tid] = psum;
    __syncthreads();
    for (int s = 128; s > 0; s >>= 1){
        if (tid < s) red[tid] += red[tid + s];
        __syncthreads();
    }
    if (tid == 0) g_PART[type*128 + blockIdx.x] = red[0];
}

__global__ void k_final(float* __restrict__ dout, int out_size)
{
    int tid = threadIdx.x;  // 32
    float s[3];
    #pragma unroll
    for (int t = 0; t < 3; t++){
        float v = 0.f;
        for (int i = tid; i < 128; i += 32) v += g_PART[t*128 + i];
        #pragma unroll
        for (int off = 16; off > 0; off >>= 1) v += __shfl_xor_sync(0xffffffffu, v, off);
        s[t] = v;
    }
    if (tid == 0 && out_size > M_TOK*DM){
        const float inv = 1.f / 16777216.f;   // 1/(4096*4096)
        dout[M_TOK*DM] = (s[0] + s[1] - 2.f*s[2]) * inv;
    }
}

// ---------------- host orchestration --------------------------------------------
extern "C" void kernel_launch(void* const* d_in, const int* in_sizes, int n_in,
                              void* d_out, int out_size)
{
    (void)in_sizes; (void)n_in;
    const float* hsi  = (const float*)d_in[0];
    const float* rgb  = (const float*)d_in[1];
    const float* in_w = (const float*)d_in[2];
    const float* in_b = (const float*)d_in[3];
    const float* ow   = (const float*)d_in[4];
    const float* ob   = (const float*)d_in[5];
    const float* l1w  = (const float*)d_in[6];
    const float* l1b  = (const float*)d_in[7];
    const float* l2w  = (const float*)d_in[8];
    const float* l2b  = (const float*)d_in[9];
    const float* n1w  = (const float*)d_in[10];
    const float* n1b  = (const float*)d_in[11];
    const float* n2w  = (const float*)d_in[12];
    const float* n2b  = (const float*)d_in[13];
    const float* mask = (const float*)d_in[14];
    float* dout = (float*)d_out;

    float *pX, *pQKV, *pATT, *pF1;
    cudaGetSymbolAddress((void**)&pX,   g_X);
    cudaGetSymbolAddress((void**)&pQKV, g_QKV);
    cudaGetSymbolAddress((void**)&pATT, g_ATT);
    cudaGetSymbolAddress((void**)&pF1,  g_F1);

    for (int l = 0; l < NLAYER; l++){
        const float* Xin = (l == 0) ? hsi : pX;
        // QKV projection (q pre-scaled), scattered to [3][NH][M][HD]
        k_gemm<64,0><<<dim3(128,3), 256>>>(Xin, 64, in_w + l*192*64, in_b + l*192,
                                           nullptr, nullptr, nullptr, pQKV, 0);
        // attention (split-K additive softmax, no-max)
        k_attn<<<dim3(32, NH, KSPLIT), 128>>>(pQKV);
        k_comb<<<1024, 256>>>(pATT);
        // out-proj + residual + LN1
        k_gemm<64,2><<<dim3(128,1), 256>>>(pATT, 64, ow + l*64*64, ob + l*64,
                                           Xin, n1w + l*64, n1b + l*64, pX, 64);
        // FF1 (ReLU)
        k_gemm<64,1><<<dim3(128,4), 256>>>(pX, 64, l1w + l*256*64, l1b + l*256,
                                           nullptr, nullptr, nullptr, pF1, 256);
        // FF2 + residual + LN2
        k_gemm<256,2><<<dim3(128,1), 256>>>(pF1, 256, l2w + l*64*256, l2b + l*64,
                                            pX, n2w + l*64, n2b + l*64, pX, 64);
    }
    // prune + write output x + row norms
    k_pn<<<4096, 64>>>(pX, rgb, mask, dout);
    // MMD gram sums (xx, yy, xy)
    k_mmd<<<dim3(128,3), 256>>>(rgb);
    k_final<<<1, 32>>>(dout, out_size);
}

// round 6
// speedup vs baseline: 1.1515x; 1.1515x over previous
#include <cuda_runtime.h>

#define M_TOK 4096
#define DM    64
#define NH    8
#define HD    8
#define DFF   256
#define NLAYER 4
#define KSPLIT 2

typedef unsigned long long u64;

// ---------------- scratch (device globals; no allocation allowed) ----------------
__device__ __align__(16) float g_X   [M_TOK*DM];
__device__ __align__(16) float g_QKV [3*NH*M_TOK*HD];
__device__ __align__(16) float g_ATT [M_TOK*DM];
__device__ __align__(16) float g_F1  [M_TOK*DFF];
__device__ __align__(16) float g_PACC[KSPLIT*M_TOK*DM];
__device__ __align__(16) float g_PSUM[KSPLIT*NH*M_TOK];
__device__ __align__(16) float g_XP  [M_TOK*DM];
__device__ float g_NX[M_TOK];
__device__ float g_NY[M_TOK];
__device__ float g_PART[3*128];
__device__ int   g_kd;

// ---------------- packed f32x2 helpers (SASS FFMA2: only reachable via PTX) ------
#define F2_FMA3(d,a,b,c) asm("fma.rn.f32x2 %0,%1,%2,%3;" : "=l"(d) : "l"(a),"l"(b),"l"(c))
#define F2_FMA(d,a,b)    asm("fma.rn.f32x2 %0,%1,%2,%0;" : "+l"(d) : "l"(a),"l"(b))
// Horner step: p = p*f + c   (dst is the multiplicand — distinct from F2_FMA!)
#define F2_HORN(p,f,c)   asm("fma.rn.f32x2 %0,%0,%1,%2;" : "+l"(p) : "l"(f),"l"(c))
#define F2_MUL(d,a,b)    asm("mul.rn.f32x2 %0,%1,%2;"    : "=l"(d) : "l"(a),"l"(b))
#define F2_ADD(d,a,b)    asm("add.rn.f32x2 %0,%1,%2;"    : "+l"(d) : "l"(a),"l"(b))
#define PACK2(d,lo,hi)   asm("mov.b64 %0,{%1,%2};" : "=l"(d) : "r"(lo),"r"(hi))
#define UNPACK2(lo,hi,s) asm("mov.b64 {%0,%1},%2;" : "=r"(lo),"=r"(hi) : "l"(s))

__device__ __forceinline__ u64 pairbits(unsigned x){
    u64 r; asm("mov.b64 %0,{%1,%1};" : "=l"(r) : "r"(x)); return r;
}

struct ExpC { u64 L2E, MAG, N1, c5, c4, c3, c2, c1, c0; };
__device__ __forceinline__ ExpC make_expc(){
    ExpC e;
    e.L2E = pairbits(0x3FB8AA3Bu);          // log2(e)
    e.MAG = pairbits(0x4B400000u);          // 12582912.f
    e.N1  = pairbits(0xBF800000u);          // -1.f
    e.c5  = pairbits(__float_as_uint(1.3333558146e-3f));
    e.c4  = pairbits(__float_as_uint(9.618129107e-3f));
    e.c3  = pairbits(__float_as_uint(5.550410866e-2f));
    e.c2  = pairbits(__float_as_uint(2.402264923e-1f));
    e.c1  = pairbits(__float_as_uint(6.9314718056e-1f));
    e.c0  = pairbits(0x3F800000u);          // 1.f
    return e;
}

// exp() on two packed floats, entirely on the FMA pipe. Inputs must be > -80.
// Returns packed pair; also exposes the raw bit halves for cheap broadcast packs.
__device__ __forceinline__ u64 pexp2(u64 s, const ExpC& C, unsigned& r0, unsigned& r1){
    u64 t, nfn, f, p;
    F2_FMA3(t,   s, C.L2E, C.MAG);   // round(x*log2e) in mantissa
    F2_FMA3(nfn, t, C.N1,  C.MAG);   // magic - t = -fn
    F2_FMA3(f,   s, C.L2E, nfn);     // frac in [-0.5, 0.5]
    F2_FMA3(p, C.c5, f, C.c4);       // p = c5*f + c4
    F2_HORN(p, f, C.c3);             // p = p*f + c3
    F2_HORN(p, f, C.c2);
    F2_HORN(p, f, C.c1);
    F2_HORN(p, f, C.c0);
    unsigned t0,t1,p0,p1;
    UNPACK2(t0,t1,t); UNPACK2(p0,p1,p);
    r0 = p0 + (t0 << 23);            // exponent splice: (magic_bits<<23) == 0 mod 2^32
    r1 = p1 + (t1 << 23);
    u64 r; PACK2(r, r0, r1);
    return r;
}

// ---------------- generic skinny GEMM: C = A[4096,K] @ W[ncols,K]^T + b ----------
// 16-row tiles (grid.x=256 -> covers all SMs), k-parity packed f32x2 accumulation.
// EPI 0: scatter to Q/K/V head layout (q scaled by 1/sqrt(hd))
// EPI 1: ReLU, store to OUT[m*ldo + col]
// EPI 2: + residual, LayerNorm -> OUT[m*64 + col]   (grid.y must be 1)
template<int KDIM, int EPI>
__global__ __launch_bounds__(256) void k_gemm(
    const float* __restrict__ A, int lda,
    const float* __restrict__ W,
    const float* __restrict__ bias,
    const float* __restrict__ RES,
    const float* __restrict__ lnw, const float* __restrict__ lnb,
    float* __restrict__ OUT, int ldo)
{
    __shared__ __align__(16) float Asm[16][68];
    __shared__ __align__(16) float Wsm[64][66];   // [col][k] so k-pairs are contiguous
    const int tid = threadIdx.x;
    const int rb  = blockIdx.x * 16;
    const int cb  = blockIdx.y * 64;
    const int c0  = tid & 31;
    const int rbase = (tid >> 5) * 2;
    u64 acc2[2][2] = {};
    const int ldq = lda >> 2;

    #pragma unroll
    for (int ch = 0; ch < KDIM/64; ch++){
        const float4* A4 = (const float4*)(A + (size_t)rb*lda + ch*64);
        {
            int r = tid >> 4, kq = tid & 15;    // 256 float4s, one per thread
            *(float4*)&Asm[r][kq*4] = A4[(size_t)r*ldq + kq];
        }
        #pragma unroll
        for (int idx = tid; idx < 4096; idx += 256){
            int c = idx >> 6, k = idx & 63;
            Wsm[c][k] = W[(size_t)(cb + c)*KDIM + ch*64 + k];
        }
        __syncthreads();
        #pragma unroll
        for (int k = 0; k < 64; k += 4){
            ulonglong2 a0 = *(const ulonglong2*)&Asm[rbase+0][k];
            ulonglong2 a1 = *(const ulonglong2*)&Asm[rbase+1][k];
            u64 w0a = *(const u64*)&Wsm[c0   ][k];
            u64 w0b = *(const u64*)&Wsm[c0   ][k+2];
            u64 w1a = *(const u64*)&Wsm[c0+32][k];
            u64 w1b = *(const u64*)&Wsm[c0+32][k+2];
            F2_FMA(acc2[0][0], a0.x, w0a); F2_FMA(acc2[0][0], a0.y, w0b);
            F2_FMA(acc2[0][1], a0.x, w1a); F2_FMA(acc2[0][1], a0.y, w1b);
            F2_FMA(acc2[1][0], a1.x, w0a); F2_FMA(acc2[1][0], a1.y, w0b);
            F2_FMA(acc2[1][1], a1.x, w1a); F2_FMA(acc2[1][1], a1.y, w1b);
        }
        __syncthreads();
    }

    const float qs = (EPI == 0 && blockIdx.y == 0) ? 0.35355339059327373f : 1.0f;
    #pragma unroll
    for (int i = 0; i < 2; i++){
        int m = rb + rbase + i;
        #pragma unroll
        for (int u = 0; u < 2; u++){
            int c = c0 + 32*u;
            unsigned lo, hi;
            UNPACK2(lo, hi, acc2[i][u]);
            float v = __uint_as_float(lo) + __uint_as_float(hi) + bias[cb + c];
            if (EPI == 0){
                v *= qs;
                int head = c >> 3, jj = c & 7;
                OUT[(((int)blockIdx.y*NH + head)*M_TOK + m)*HD + jj] = v;
            } else if (EPI == 1){
                OUT[(size_t)m*ldo + cb + c] = fmaxf(v, 0.f);
            } else {
                Asm[rbase+i][c] = v + RES[m*DM + c];
            }
        }
    }
    if (EPI == 2){
        __syncthreads();
        int row = tid >> 4, seg = tid & 15;    // 16 lanes per row, 4 cols each
        float s = 0.f, s2 = 0.f;
        #pragma unroll
        for (int t = 0; t < 4; t++){
            float x = Asm[row][seg*4 + t];
            s += x; s2 = fmaf(x, x, s2);
        }
        #pragma unroll
        for (int off = 8; off > 0; off >>= 1){
            s  += __shfl_xor_sync(0xffffffffu, s,  off);
            s2 += __shfl_xor_sync(0xffffffffu, s2, off);
        }
        float mean = s * (1.f/64.f);
        float var  = fmaf(-mean, mean, s2 * (1.f/64.f));
        float rstd = rsqrtf(var + 1e-5f);
        int m = rb + row;
        #pragma unroll
        for (int t = 0; t < 4; t++){
            int c = seg*4 + t;
            OUT[m*DM + c] = (Asm[row][c] - mean) * rstd * lnw[c] + lnb[c];
        }
    }
}

// ---------------- attention: no-max softmax, additive split-K, f32x2 2-key loop --
// K tile stored pair-interleaved: Kp[jp*16 + d*2 + parity] so LDS.128 yields
// packed (k_even[d], k_odd[d]) operands directly.
__global__ __launch_bounds__(128) void k_attn(const float* __restrict__ QKV)
{
    __shared__ __align__(16) float  Kp[512*8];
    __shared__ __align__(16) float4 Vs[512*2];
    const int tid = threadIdx.x;
    const int h   = blockIdx.y;
    const int m   = blockIdx.x*128 + tid;
    const int ks  = blockIdx.z;
    const float4* Q4 = (const float4*)QKV + (size_t)(h*M_TOK + m)*2;
    const float4* K4 = (const float4*)QKV + (size_t)(NH*M_TOK + h*M_TOK)*2;
    const float4* V4 = (const float4*)QKV + (size_t)(2*NH*M_TOK + h*M_TOK)*2;

    const ExpC C = make_expc();
    float4 q0 = Q4[0], q1 = Q4[1];
    u64 qp[8];
    qp[0]=pairbits(__float_as_uint(q0.x)); qp[1]=pairbits(__float_as_uint(q0.y));
    qp[2]=pairbits(__float_as_uint(q0.z)); qp[3]=pairbits(__float_as_uint(q0.w));
    qp[4]=pairbits(__float_as_uint(q1.x)); qp[5]=pairbits(__float_as_uint(q1.y));
    qp[6]=pairbits(__float_as_uint(q1.z)); qp[7]=pairbits(__float_as_uint(q1.w));

    u64 acc[4] = {0,0,0,0};      // out dims (0,1)(2,3)(4,5)(6,7)
    u64 ssum2  = 0;

    for (int kt = 0; kt < 4; kt++){
        int key0 = ks*2048 + kt*512;
        for (int idx = tid; idx < 1024; idx += 128){
            int j = idx >> 1, hf = idx & 1;
            float4 kv = K4[key0*2 + idx];
            float* dst = Kp + (j>>1)*16 + hf*8 + (j&1);
            dst[0]=kv.x; dst[2]=kv.y; dst[4]=kv.z; dst[6]=kv.w;
            Vs[idx] = V4[key0*2 + idx];
        }
        __syncthreads();
        const ulonglong2* vr = (const ulonglong2*)Vs;
        #pragma unroll 2
        for (int jp = 0; jp < 256; jp++){
            const ulonglong2* kr = (const ulonglong2*)(Kp + jp*16);
            ulonglong2 k01 = kr[0], k23 = kr[1], k45 = kr[2], k67 = kr[3];
            u64 s2;
            F2_MUL(s2, qp[0], k01.x);
            F2_FMA(s2, qp[1], k01.y);
            F2_FMA(s2, qp[2], k23.x);
            F2_FMA(s2, qp[3], k23.y);
            F2_FMA(s2, qp[4], k45.x);
            F2_FMA(s2, qp[5], k45.y);
            F2_FMA(s2, qp[6], k67.x);
            F2_FMA(s2, qp[7], k67.y);
            unsigned r0, r1;
            u64 p2 = pexp2(s2, C, r0, r1);
            F2_ADD(ssum2, ssum2, p2);
            u64 pb0 = pairbits(r0);
            u64 pb1 = pairbits(r1);
            ulonglong2 e0 = vr[4*jp],   e1 = vr[4*jp+1];   // even key d0-3, d4-7
            ulonglong2 o0 = vr[4*jp+2], o1 = vr[4*jp+3];   // odd key
            F2_FMA(acc[0], pb0, e0.x); F2_FMA(acc[1], pb0, e0.y);
            F2_FMA(acc[2], pb0, e1.x); F2_FMA(acc[3], pb0, e1.y);
            F2_FMA(acc[0], pb1, o0.x); F2_FMA(acc[1], pb1, o0.y);
            F2_FMA(acc[2], pb1, o1.x); F2_FMA(acc[3], pb1, o1.y);
        }
        __syncthreads();
    }
    u64* PA = (u64*)(g_PACC + (size_t)ks*M_TOK*DM + (size_t)m*DM + h*HD);
    PA[0]=acc[0]; PA[1]=acc[1]; PA[2]=acc[2]; PA[3]=acc[3];
    unsigned slo, shi; UNPACK2(slo, shi, ssum2);
    g_PSUM[ks*NH*M_TOK + h*M_TOK + m] = __uint_as_float(slo) + __uint_as_float(shi);
}

__global__ __launch_bounds__(256) void k_comb(float* __restrict__ ATT)
{
    int idx = blockIdx.x*256 + threadIdx.x;
    int m = idx >> 6, c = idx & 63, h = c >> 3;
    float s = g_PSUM[h*M_TOK + m] + g_PSUM[NH*M_TOK + h*M_TOK + m];
    ATT[idx] = (g_PACC[idx] + g_PACC[M_TOK*DM + idx]) / s;
}

// ---------------- prune + row norms (+ detect mask support, for dot shortcut) ---
__global__ __launch_bounds__(64) void k_pn(const float* __restrict__ X,
                                           const float* __restrict__ RGB,
                                           const float* __restrict__ mask,
                                           float* __restrict__ dout)
{
    __shared__ float w0x, w0y;
    __shared__ int anyhi;
    int r = blockIdx.x, d = threadIdx.x;
    float xv = X[r*DM + d] * mask[d];
    g_XP[r*DM + d] = xv;
    dout[r*DM + d] = xv;
    float yv = RGB[r*DM + d];
    float sx = xv*xv, sy = yv*yv;
    #pragma unroll
    for (int off = 16; off > 0; off >>= 1){
        sx += __shfl_xor_sync(0xffffffffu, sx, off);
        sy += __shfl_xor_sync(0xffffffffu, sy, off);
    }
    if (d == 0){ w0x = sx; w0y = sy; }
    if (r == 0 && d == 0) anyhi = 0;
    __syncthreads();
    if (d == 32){ g_NX[r] = w0x + sx; g_NY[r] = w0y + sy; }
    if (r == 0){
        if (d >= 32 && mask[d] != 0.f) anyhi = 1;
        __syncthreads();
        if (d == 0) g_kd = anyhi ? 64 : 32;
    }
}

// ---------------- Gaussian-kernel gram sums (f32x2 dots over k-parity) ----------
template<int KD>
__device__ __forceinline__ u64 mmd_tile(const float (*Asm)[68], const float (*Bsm)[68],
                                        const float* na, const float* nb,
                                        int rbase, int ja, const ExpC& C)
{
    u64 acc2[4][4] = {};
    #pragma unroll
    for (int k = 0; k < KD; k += 4){
        ulonglong2 a0 = *(const ulonglong2*)&Asm[rbase+0][k];
        ulonglong2 a1 = *(const ulonglong2*)&Asm[rbase+1][k];
        ulonglong2 a2 = *(const ulonglong2*)&Asm[rbase+2][k];
        ulonglong2 a3 = *(const ulonglong2*)&Asm[rbase+3][k];
        ulonglong2 b0 = *(const ulonglong2*)&Bsm[ja    ][k];
        ulonglong2 b1 = *(const ulonglong2*)&Bsm[ja+32 ][k];
        ulonglong2 b2 = *(const ulonglong2*)&Bsm[ja+64 ][k];
        ulonglong2 b3 = *(const ulonglong2*)&Bsm[ja+96 ][k];
        F2_FMA(acc2[0][0], a0.x, b0.x); F2_FMA(acc2[0][0], a0.y, b0.y);
        F2_FMA(acc2[0][1], a0.x, b1.x); F2_FMA(acc2[0][1], a0.y, b1.y);
        F2_FMA(acc2[0][2], a0.x, b2.x); F2_FMA(acc2[0][2], a0.y, b2.y);
        F2_FMA(acc2[0][3], a0.x, b3.x); F2_FMA(acc2[0][3], a0.y, b3.y);
        F2_FMA(acc2[1][0], a1.x, b0.x); F2_FMA(acc2[1][0], a1.y, b0.y);
        F2_FMA(acc2[1][1], a1.x, b1.x); F2_FMA(acc2[1][1], a1.y, b1.y);
        F2_FMA(acc2[1][2], a1.x, b2.x); F2_FMA(acc2[1][2], a1.y, b2.y);
        F2_FMA(acc2[1][3], a1.x, b3.x); F2_FMA(acc2[1][3], a1.y, b3.y);
        F2_FMA(acc2[2][0], a2.x, b0.x); F2_FMA(acc2[2][0], a2.y, b0.y);
        F2_FMA(acc2[2][1], a2.x, b1.x); F2_FMA(acc2[2][1], a2.y, b1.y);
        F2_FMA(acc2[2][2], a2.x, b2.x); F2_FMA(acc2[2][2], a2.y, b2.y);
        F2_FMA(acc2[2][3], a2.x, b3.x); F2_FMA(acc2[2][3], a2.y, b3.y);
        F2_FMA(acc2[3][0], a3.x, b0.x); F2_FMA(acc2[3][0], a3.y, b0.y);
        F2_FMA(acc2[3][1], a3.x, b1.x); F2_FMA(acc2[3][1], a3.y, b1.y);
        F2_FMA(acc2[3][2], a3.x, b2.x); F2_FMA(acc2[3][2], a3.y, b2.y);
        F2_FMA(acc2[3][3], a3.x, b3.x); F2_FMA(acc2[3][3], a3.y, b3.y);
    }
    u64 psum2 = 0;
    #pragma unroll
    for (int i = 0; i < 4; i++){
        float nai = na[rbase+i];
        float x[4];
        #pragma unroll
        for (int u = 0; u < 4; u++){
            unsigned lo, hi; UNPACK2(lo, hi, acc2[i][u]);
            float dot = __uint_as_float(lo) + __uint_as_float(hi);
            float d = nai + nb[ja + 32*u] - 2.f*dot;
            x[u] = fminf(d, 150.f) * -0.5f;    // clamp keeps exponent splice valid
        }
        u64 s01, s23;
        PACK2(s01, __float_as_uint(x[0]), __float_as_uint(x[1]));
        PACK2(s23, __float_as_uint(x[2]), __float_as_uint(x[3]));
        unsigned d0, d1;
        u64 p01 = pexp2(s01, C, d0, d1);
        u64 p23 = pexp2(s23, C, d0, d1);
        F2_ADD(psum2, psum2, p01);
        F2_ADD(psum2, psum2, p23);
    }
    return psum2;
}

__global__ __launch_bounds__(256) void k_mmd(const float* __restrict__ RGB)
{
    __shared__ __align__(16) float Asm[32][68];
    __shared__ __align__(16) float Bsm[128][68];
    __shared__ float na[32], nb[128], red[256];
    const int type = blockIdx.y;
    const float *A, *B, *NA, *NB;
    if (type == 0){ A = g_XP; B = g_XP; NA = g_NX; NB = g_NX; }
    else if (type == 1){ A = RGB; B = RGB; NA = g_NY; NB = g_NY; }
    else { A = g_XP; B = RGB; NA = g_NX; NB = g_NY; }
    const int kd = (type == 1) ? 64 : g_kd;
    const ExpC C = make_expc();

    const int tid = threadIdx.x;
    const int ib  = blockIdx.x * 32;
    for (int idx = tid; idx < 512; idx += 256){
        int r = idx >> 4, kq = idx & 15;
        *(float4*)&Asm[r][kq*4] = ((const float4*)A)[(ib + r)*16 + kq];
    }
    if (tid < 32) na[tid] = NA[ib + tid];

    const int ja = tid & 31, rbase = (tid >> 5) * 4;
    u64 psum2 = 0;
    for (int jt = 0; jt < 32; jt++){
        __syncthreads();
        for (int idx = tid; idx < 2048; idx += 256){
            int r = idx >> 4, kq = idx & 15;
            *(float4*)&Bsm[r][kq*4] = ((const float4*)B)[(jt*128 + r)*16 + kq];
        }
        if (tid < 128) nb[tid] = NB[jt*128 + tid];
        __syncthreads();
        u64 t;
        if (kd == 32) t = mmd_tile<32>(Asm, Bsm, na, nb, rbase, ja, C);
        else          t = mmd_tile<64>(Asm, Bsm, na, nb, rbase, ja, C);
        F2_ADD(psum2, psum2, t);
    }
    unsigned lo, hi; UNPACK2(lo, hi, psum2);
    red[tid] = __uint_as_float(lo) + __uint_as_float(hi);
    __syncthreads();
    for (int s = 128; s > 0; s >>= 1){
        if (tid < s) red[tid] += red[tid + s];
        __syncthreads();
    }
    if (tid == 0) g_PART[type*128 + blockIdx.x] = red[0];
}

__global__ void k_final(float* __restrict__ dout, int out_size)
{
    int tid = threadIdx.x;  // 32
    float s[3];
    #pragma unroll
    for (int t = 0; t < 3; t++){
        float v = 0.f;
        for (int i = tid; i < 128; i += 32) v += g_PART[t*128 + i];
        #pragma unroll
        for (int off = 16; off > 0; off >>= 1) v += __shfl_xor_sync(0xffffffffu, v, off);
        s[t] = v;
    }
    if (tid == 0 && out_size > M_TOK*DM){
        const float inv = 1.f / 16777216.f;   // 1/(4096*4096)
        dout[M_TOK*DM] = (s[0] + s[1] - 2.f*s[2]) * inv;
    }
}

// ---------------- host orchestration --------------------------------------------
extern "C" void kernel_launch(void* const* d_in, const int* in_sizes, int n_in,
                              void* d_out, int out_size)
{
    (void)in_sizes; (void)n_in;
    const float* hsi  = (const float*)d_in[0];
    const float* rgb  = (const float*)d_in[1];
    const float* in_w = (const float*)d_in[2];
    const float* in_b = (const float*)d_in[3];
    const float* ow   = (const float*)d_in[4];
    const float* ob   = (const float*)d_in[5];
    const float* l1w  = (const float*)d_in[6];
    const float* l1b  = (const float*)d_in[7];
    const float* l2w  = (const float*)d_in[8];
    const float* l2b  = (const float*)d_in[9];
    const float* n1w  = (const float*)d_in[10];
    const float* n1b  = (const float*)d_in[11];
    const float* n2w  = (const float*)d_in[12];
    const float* n2b  = (const float*)d_in[13];
    const float* mask = (const float*)d_in[14];
    float* dout = (float*)d_out;

    float *pX, *pQKV, *pATT, *pF1;
    cudaGetSymbolAddress((void**)&pX,   g_X);
    cudaGetSymbolAddress((void**)&pQKV, g_QKV);
    cudaGetSymbolAddress((void**)&pATT, g_ATT);
    cudaGetSymbolAddress((void**)&pF1,  g_F1);

    for (int l = 0; l < NLAYER; l++){
        const float* Xin = (l == 0) ? hsi : pX;
        // QKV projection (q pre-scaled), scattered to [3][NH][M][HD]
        k_gemm<64,0><<<dim3(256,3), 256>>>(Xin, 64, in_w + l*192*64, in_b + l*192,
                                           nullptr, nullptr, nullptr, pQKV, 0);
        // attention (split-K additive softmax, no-max, f32x2 2-key inner loop)
        k_attn<<<dim3(32, NH, KSPLIT), 128>>>(pQKV);
        k_comb<<<1024, 256>>>(pATT);
        // out-proj + residual + LN1
        k_gemm<64,2><<<dim3(256,1), 256>>>(pATT, 64, ow + l*64*64, ob + l*64,
                                           Xin, n1w + l*64, n1b + l*64, pX, 64);
        // FF1 (ReLU)
        k_gemm<64,1><<<dim3(256,4), 256>>>(pX, 64, l1w + l*256*64, l1b + l*256,
                                           nullptr, nullptr, nullptr, pF1, 256);
        // FF2 + residual + LN2
        k_gemm<256,2><<<dim3(256,1), 256>>>(pF1, 256, l2w + l*64*256, l2b + l*64,
                                            pX, n2w + l*64, n2b + l*64, pX, 64);
    }
    // prune + write output x + row norms
    k_pn<<<4096, 64>>>(pX, rgb, mask, dout);
    // MMD gram sums (xx, yy, xy)
    k_mmd<<<dim3(128,3), 256>>>(rgb);
    k_final<<<1, 32>>>(dout, out_size);
}